// round 14
// baseline (speedup 1.0000x reference)
#include <cuda_runtime.h>

typedef unsigned int u32;
typedef unsigned short u16;

__device__ float g_b0[32u * 128 * 128 * 128];
__device__ float g_b1[32u * 256 * 64 * 64];
__device__ float g_b2[32u * 512 * 32 * 32];
__device__ float g_b3[32u * 32 * 64 * 64];
__device__ float g_ze[32u * 64 * 32 * 32];
__device__ float g_loss[1];
__device__ u32   g_wt[2097152];
__device__ u32   g_mx[4359168];    // enc1 in: 128 x 258 x 132 u32
__device__ u32   g_m0[36218880];   // enc2 in / dec3 in: 4096 x 130 x 68 u32
__device__ u32   g_m1[19464192];   // enc3-in / dec-res / dec2-in: 8192 x 66 x 36
__device__ u32   g_me[11141120];   // enc-res: 16384 x 34 x 20 u32
__device__ u32   g_mq[1392640];    // dec1 in: 2048 x 34 x 20 u32

__device__ __forceinline__ u32 pack_f16x2(float lo, float hi) {
    u32 r; asm("cvt.rn.f16x2.f32 %0,%1,%2;" : "=r"(r) : "f"(hi), "f"(lo)); return r;
}
__device__ __forceinline__ u16 f2h(float f) {
    u16 h; asm("cvt.rn.f16.f32 %0,%1;" : "=h"(h) : "f"(f)); return h;
}
__device__ __forceinline__ float h2f(u16 h) {
    float f; asm("cvt.f32.f16 %0,%1;" : "=f"(f) : "h"(h)); return f;
}
__device__ __forceinline__ u32 prmt(u32 a, u32 b, u32 s) {
    u32 r; asm("prmt.b32 %0,%1,%2,%3;" : "=r"(r) : "r"(a), "r"(b), "r"(s)); return r;
}
__device__ __forceinline__ u32 smem_u32(const void* p) {
    u32 a; asm("{ .reg .u64 t; cvta.to.shared.u64 t,%1; cvt.u32.u64 %0,t; }"
               : "=r"(a) : "l"(p));
    return a;
}

#define CP_A16(d, s) asm volatile("cp.async.ca.shared.global [%0],[%1],16;" :: "r"(d), "l"(s))
#define CP_A4(d, s)  asm volatile("cp.async.ca.shared.global [%0],[%1],4;"  :: "r"(d), "l"(s))
#define CP_COMMIT()  asm volatile("cp.async.commit_group;" ::: "memory")
#define CP_WAIT0()   asm volatile("cp.async.wait_group 0;" ::: "memory")
#define CP_WAIT1()   asm volatile("cp.async.wait_group 1;" ::: "memory")

#define MMA_F16(d, a0, a1, a2, a3, b0, b1)                                    \
    asm volatile("mma.sync.aligned.m16n8k16.row.col.f32.f16.f16.f32 "         \
                 "{%0,%1,%2,%3},{%4,%5,%6,%7},{%8,%9},{%0,%1,%2,%3};"         \
                 : "+f"(d[0]), "+f"(d[1]), "+f"(d[2]), "+f"(d[3])             \
                 : "r"(a0), "r"(a1), "r"(a2), "r"(a3), "r"(b0), "r"(b1))

// ---- mirror build (network input only) -------------------------------------
__global__ void cvt_mirror(const float* __restrict__ src, u32* __restrict__ dst,
                           int Hi, int Wi, int Hp, int Wp2, int relu,
                           int scpb, int dshift)
{
    const int plane = blockIdx.y;
    const int idx = blockIdx.x * 256 + threadIdx.x;
    if (idx >= Hp * Wp2) return;
    const int ph = idx / Wp2, wp2 = idx - ph * Wp2;
    const int b = plane >> dshift;
    const int c = plane & ((1 << dshift) - 1);
    const int ih = ph - 1;
    const int iw0 = 2 * wp2 - 1, iw1 = iw0 + 1;
    float v0 = 0.f, v1 = 0.f;
    if (c < scpb && (unsigned)ih < (unsigned)Hi) {
        const float* r = src + ((size_t)(b * scpb + c) * Hi + ih) * Wi;
        if ((unsigned)iw0 < (unsigned)Wi) v0 = r[iw0];
        if ((unsigned)iw1 < (unsigned)Wi) v1 = r[iw1];
    }
    if (relu) { v0 = fmaxf(v0, 0.f); v1 = fmaxf(v1, 0.f); }
    dst[(size_t)plane * Hp * Wp2 + idx] = pack_f16x2(v0, v1);
}

// ===========================================================================
// conv1x1 fp32 — optional fused mirror output
// ===========================================================================

__global__ void __launch_bounds__(256) conv1x1_kernel(
    const float* __restrict__ in, const float* __restrict__ w,
    const float* __restrict__ bias, float* __restrict__ out,
    int Ci, int Co, int P, int relu_in, int add_res,
    int wout, u16* __restrict__ mout, int MHp, int MWp, int hw_shift, int hwm)
{
    __shared__ float w_s[16][64];
    __shared__ float x_s[16][64];
    const int tid = threadIdx.x;
    const int tx = tid & 15, ty = tid >> 4;
    const int p0 = blockIdx.x * 64, c0 = blockIdx.y * 64, b = blockIdx.z;

    float acc[4][4];
#pragma unroll
    for (int i = 0; i < 4; i++)
#pragma unroll
        for (int j = 0; j < 4; j++) acc[i][j] = 0.f;

    for (int ci0 = 0; ci0 < Ci; ci0 += 16) {
        for (int idx = tid; idx < 1024; idx += 256) {
            int p = idx & 63, ci = idx >> 6;
            float v = in[(size_t)(b * Ci + ci0 + ci) * P + p0 + p];
            x_s[ci][p] = relu_in ? fmaxf(v, 0.f) : v;
        }
        for (int idx = tid; idx < 1024; idx += 256) {
            int ci = idx & 15, co = idx >> 4;
            w_s[ci][co] = w[(size_t)(c0 + co) * Ci + ci0 + ci];
        }
        __syncthreads();
#pragma unroll
        for (int ci = 0; ci < 16; ci++) {
            const float4 wv = *(const float4*)&w_s[ci][ty << 2];
            const float4 xv = *(const float4*)&x_s[ci][tx << 2];
            const float wvv[4] = {wv.x, wv.y, wv.z, wv.w};
            const float xvv[4] = {xv.x, xv.y, xv.z, xv.w};
#pragma unroll
            for (int i = 0; i < 4; i++)
#pragma unroll
                for (int j = 0; j < 4; j++)
                    acc[i][j] = fmaf(wvv[i], xvv[j], acc[i][j]);
        }
        __syncthreads();
    }
#pragma unroll
    for (int i = 0; i < 4; i++) {
        const int co = c0 + (ty << 2) + i;
        const float bv = bias ? bias[co] : 0.f;
        const int px = p0 + (tx << 2);
        const size_t base = (size_t)(b * Co + co) * P + px;
        float4 o = {acc[i][0] + bv, acc[i][1] + bv, acc[i][2] + bv, acc[i][3] + bv};
        if (add_res) {
            float4 rr = *(const float4*)&out[base];
            o.x += rr.x; o.y += rr.y; o.z += rr.z; o.w += rr.w;
        }
        if (wout) *(float4*)&out[base] = o;
        if (mout) {
            const int oh = px >> hw_shift, ow = px & hwm;
            u16* mp = mout + ((size_t)(b * Co + co) * MHp + oh + 1) * MWp + ow + 1;
            mp[0] = f2h(fmaxf(o.x, 0.f));
            mp[1] = f2h(fmaxf(o.y, 0.f));
            mp[2] = f2h(fmaxf(o.z, 0.f));
            mp[3] = f2h(fmaxf(o.w, 0.f));
        }
    }
}

// ===========================================================================
// VQ — writes dec1 mirror directly
// ===========================================================================

__global__ void __launch_bounds__(256) vq_kernel(
    const float* __restrict__ ze, const float* __restrict__ emb,
    u16* __restrict__ mq, float* __restrict__ loss)
{
    __shared__ float e_s[128 * 64];
    __shared__ float n_s[128];
    const int tid = threadIdx.x;
    const int n = blockIdx.x * 256 + tid;
    const int b = n >> 10, hw = n & 1023;

    float xr[64];
#pragma unroll
    for (int d = 0; d < 64; d++)
        xr[d] = ze[((size_t)(b * 64 + d) << 10) + hw];

    float best = 3.4e38f;
    int bi = 0;
    for (int kb = 0; kb < 4; kb++) {
        __syncthreads();
        for (int i = tid; i < 128 * 64; i += 256) e_s[i] = emb[kb * 128 * 64 + i];
        __syncthreads();
        if (tid < 128) {
            float s = 0.f;
#pragma unroll 8
            for (int d = 0; d < 64; d++) { float v = e_s[tid * 64 + d]; s = fmaf(v, v, s); }
            n_s[tid] = s;
        }
        __syncthreads();
        for (int k = 0; k < 128; k++) {
            const float4* e4 = (const float4*)(e_s + k * 64);
            float dot = 0.f;
#pragma unroll
            for (int d4 = 0; d4 < 16; d4++) {
                float4 e = e4[d4];
                dot = fmaf(e.x, xr[d4 * 4 + 0], dot);
                dot = fmaf(e.y, xr[d4 * 4 + 1], dot);
                dot = fmaf(e.z, xr[d4 * 4 + 2], dot);
                dot = fmaf(e.w, xr[d4 * 4 + 3], dot);
            }
            float dist = n_s[k] - 2.f * dot;
            if (dist < best) { best = dist; bi = kb * 128 + k; }
        }
    }

    const int oh = hw >> 5, ow = hw & 31;
    float ls = 0.f;
#pragma unroll
    for (int d = 0; d < 64; d++) {
        float e = emb[bi * 64 + d];
        mq[((size_t)(b * 64 + d) * 34 + oh + 1) * 40 + ow + 1] = f2h(e);
        float df = e - xr[d];
        ls = fmaf(df, df, ls);
    }
#pragma unroll
    for (int o = 16; o > 0; o >>= 1) ls += __shfl_down_sync(0xffffffffu, ls, o);
    if ((tid & 31) == 0) atomicAdd(loss, ls);
}

// ===========================================================================
// dec3: fp32 parity-quad tconv, mirror(fp16) input, Co=3
// ===========================================================================

__global__ void __launch_bounds__(256) tconv3_f32(
    const u16* __restrict__ mir, const float* __restrict__ w,
    const float* __restrict__ bias, float* __restrict__ out)
{
    const int Ci = 128, Co = 3, Hi = 128, Wi = 128;
    const int MHp = 130, MWp = 136;
    const int Ho = 256, Wo2 = 256;
    __shared__ float w_s[4][16][4];
    __shared__ float x_s[4][18][18];

    const int tid = threadIdx.x;
    const int slot = tid & 63, cg = tid >> 6;     // 64 slots x 4 co-groups
    const int m_loc = slot >> 2;
    const int nb = (slot & 3) << 2;
    const int n0 = blockIdx.x * 16, m0t = blockIdx.y * 16;
    const int b = blockIdx.z;

    float acc[4][2][2];
#pragma unroll
    for (int q = 0; q < 4; q++)
#pragma unroll
        for (int a = 0; a < 2; a++)
#pragma unroll
            for (int bb = 0; bb < 2; bb++) acc[q][a][bb] = 0.f;

    for (int ci0 = 0; ci0 < Ci; ci0 += 4) {
        for (int idx = tid; idx < 4 * 18 * 18; idx += 256) {
            int lc = idx % 18;
            int t = idx / 18;
            int lr = t % 18, ci = t / 18;
            x_s[ci][lr][lc] = h2f(
                mir[((size_t)(b * Ci + ci0 + ci) * MHp + m0t + lr) * MWp + n0 + lc]);
        }
        for (int idx = tid; idx < 4 * 16 * 3; idx += 256) {
            int co = idx % 3;
            int t = (idx / 3) & 15;
            int ci = idx / 48;
            w_s[ci][t][co] = w[((size_t)(ci0 + ci) * Co + co) * 16 + t];
        }
        __syncthreads();
#pragma unroll
        for (int ci = 0; ci < 4; ci++)
#pragma unroll
            for (int t = 0; t < 16; t++) {
                const int kh = t >> 2, kw = t & 3;
                const int a = 1 - (kh & 1);
                const int dm = (kh == 0) ? 1 : ((kh == 3) ? -1 : 0);
                const int bb = 1 - (kw & 1);
                const int dn = (kw == 0) ? 1 : ((kw == 3) ? -1 : 0);
                const float wv = w_s[ci][t][cg];
                const float* xrow = &x_s[ci][m_loc + dm + 1][nb + dn + 1];
#pragma unroll
                for (int q = 0; q < 4; q++)
                    acc[q][a][bb] = fmaf(wv, xrow[q], acc[q][a][bb]);
            }
        __syncthreads();
    }

    if (cg < 3) {
        const int m = m0t + m_loc;
        const float bv = bias[cg];
#pragma unroll
        for (int q = 0; q < 4; q++) {
            const int nn = n0 + nb + q;
#pragma unroll
            for (int a = 0; a < 2; a++) {
                float2 o = {acc[q][a][0] + bv, acc[q][a][1] + bv};
                *(float2*)&out[((size_t)(b * Co + cg) * Ho + 2 * m + a) * Wo2 + 2 * nn] = o;
            }
        }
    }
}

__global__ void zero_loss_kernel(float* loss) { loss[0] = 0.f; }
__global__ void finish_loss_kernel(const float* __restrict__ loss, float* __restrict__ dst)
{
    dst[0] = 2.f * loss[0] / 2097152.f;
}

// ===========================================================================
// weight prepacks (fp16)
// ===========================================================================

__global__ void wt4s2_f16(const float* __restrict__ w, u32* __restrict__ wT2,
                          int Ci, int Co, int Ci_src)
{
    int idx = blockIdx.x * 256 + threadIdx.x;
    if (idx >= Ci * 8 * Co) return;
    int co = idx % Co, k2 = idx / Co;
    int k = 2 * k2, ci = k >> 4, t = k & 15;
    float v0 = 0.f, v1 = 0.f;
    if (ci < Ci_src) {
        const float* base = &w[((size_t)co * Ci_src + ci) * 16 + t];
        v0 = base[0]; v1 = base[1];
    }
    wT2[idx] = pack_f16x2(v0, v1);
}

__global__ void wtT_f16(const float* __restrict__ w, u32* __restrict__ wT2,
                        int Ci, int Co)
{
    int K2 = Ci * 2;
    int idx = blockIdx.x * 256 + threadIdx.x;
    if (idx >= 4 * K2 * Co) return;
    int co = idx % Co, rr = idx / Co;
    int p = rr / K2, k2 = rr % K2;
    int k = 2 * k2, ci = k >> 2, j = k & 3;
    int a = p >> 1, bb = p & 1;
    int kh = (1 - a) + 2 * (j >> 1);
    const float* base = &w[((size_t)ci * Co + co) * 16 + kh * 4];
    wT2[idx] = pack_f16x2(base[1 - bb], base[3 - bb]);
}

__global__ void wt3_f16(const float* __restrict__ w, u32* __restrict__ wT2, int Ci)
{
    int K = Ci * 9;
    int idx = blockIdx.x * 256 + threadIdx.x;
    if (idx >= (K / 2) * 32) return;
    int co = idx & 31, k2 = idx >> 5;
    int k0 = 2 * k2, k1 = k0 + 1;
    int ci0 = k0 / 9, t0 = k0 - ci0 * 9;
    int ci1 = k1 / 9, t1 = k1 - ci1 * 9;
    wT2[idx] = pack_f16x2(w[((size_t)co * Ci + ci0) * 9 + t0],
                          w[((size_t)co * Ci + ci1) * 9 + t1]);
}

// ===========================================================================
// HMMA conv k4 s2 p1 — fused mirror epilogue
// ===========================================================================

#define CHBUF 4352

__global__ void __launch_bounds__(128, 2) conv4s2_tcf(
    const u32* __restrict__ mir, const u32* __restrict__ wT2,
    const float* __restrict__ bias, float* __restrict__ out,
    int Ci, int Co, int Hp, int Wp2, int Ho, int Wo, int w_shift, int relu,
    int wout, u16* __restrict__ mout, int MHp, int MWp)
{
    extern __shared__ u32 sm[];
    const int tid = threadIdx.x;
    const int lane = tid & 31, warp = tid >> 5;
    const int gid = lane >> 2, tig = lane & 3;
    const int m0w = (warp & 1) * 64, n0w = (warp >> 1) * 64;
    const int OWT = 1 << w_shift;
    const int ow0 = blockIdx.x * OWT, oh0 = blockIdx.y * (128 >> w_shift);
    const int cot = Co >> 7;
    const int b = blockIdx.z / cot, c0 = (blockIdx.z % cot) << 7;
    const int K = Ci << 4, NC = K >> 6;
    const int sk = tid >> 2, sn0 = (tid & 3) << 5;
    const int oh = oh0 + (sn0 >> w_shift), ow = ow0 + (sn0 & (OWT - 1));
    const u32 sb = smem_u32(sm);

    auto stage = [&](int c, int buf) {
        const int k02 = c << 5;
#pragma unroll
        for (int q = 0; q < 8; q++) {
            int idx = tid + (q << 7);
            int kk = idx >> 5, m4 = idx & 31;
            u32 dst = sb + ((u32)(buf * CHBUF + kk * 136 + (m4 << 2)) << 2);
            CP_A16(dst, wT2 + (size_t)(k02 + kk) * Co + c0 + (m4 << 2));
        }
        const int k = (c << 6) + 2 * sk;
        const int ci = k >> 4, t = k & 15, kh = t >> 2, a1 = (t & 3) >> 1;
        const u32* src = mir + ((size_t)(b * Ci + ci) * Hp + 2 * oh + kh) * Wp2 + ow + a1;
        u32 dst = sb + ((u32)(2 * CHBUF + buf * CHBUF + sk * 136 + sn0) << 2);
        if (!a1) {
#pragma unroll
            for (int j = 0; j < 8; j++) CP_A16(dst + 16 * j, src + 4 * j);
        } else {
#pragma unroll
            for (int j = 0; j < 32; j++) CP_A4(dst + 4 * j, src + j);
        }
    };

    float acc[4][8][4];
#pragma unroll
    for (int mi = 0; mi < 4; mi++)
#pragma unroll
        for (int ni = 0; ni < 8; ni++)
#pragma unroll
            for (int c = 0; c < 4; c++) acc[mi][ni][c] = 0.f;

    stage(0, 0);
    CP_COMMIT();

    for (int c = 0; c < NC; c++) {
        if (c + 1 < NC) { stage(c + 1, (c + 1) & 1); CP_COMMIT(); CP_WAIT1(); }
        else CP_WAIT0();
        __syncthreads();
        const u32* As = sm + (c & 1) * CHBUF;
        const u32* Bs = sm + 2 * CHBUF + (c & 1) * CHBUF;
#pragma unroll
        for (int s = 0; s < 4; s++) {
            const int k2b = s * 8;
            u32 a[4][4], bf[8][2];
#pragma unroll
            for (int mi = 0; mi < 4; mi++) {
                a[mi][0] = As[(k2b + tig) * 136 + m0w + mi * 16 + gid];
                a[mi][1] = As[(k2b + tig) * 136 + m0w + mi * 16 + gid + 8];
                a[mi][2] = As[(k2b + tig + 4) * 136 + m0w + mi * 16 + gid];
                a[mi][3] = As[(k2b + tig + 4) * 136 + m0w + mi * 16 + gid + 8];
            }
#pragma unroll
            for (int ni = 0; ni < 8; ni++) {
                bf[ni][0] = Bs[(k2b + tig) * 136 + n0w + ni * 8 + gid];
                bf[ni][1] = Bs[(k2b + tig + 4) * 136 + n0w + ni * 8 + gid];
            }
#pragma unroll
            for (int mi = 0; mi < 4; mi++)
#pragma unroll
                for (int ni = 0; ni < 8; ni++)
                    MMA_F16(acc[mi][ni], a[mi][0], a[mi][1], a[mi][2], a[mi][3],
                            bf[ni][0], bf[ni][1]);
        }
        __syncthreads();
    }

#pragma unroll
    for (int mi = 0; mi < 4; mi++)
#pragma unroll
        for (int h = 0; h < 2; h++) {
            const int co = c0 + m0w + mi * 16 + gid + h * 8;
            const float bv = bias[co];
#pragma unroll
            for (int ni = 0; ni < 8; ni++) {
                const int n = n0w + ni * 8 + 2 * tig;
                const int ohl = n >> w_shift, owl = n & (OWT - 1);
                float v0 = acc[mi][ni][h * 2] + bv;
                float v1 = acc[mi][ni][h * 2 + 1] + bv;
                if (wout) {
                    float2 o = {relu ? fmaxf(v0, 0.f) : v0, relu ? fmaxf(v1, 0.f) : v1};
                    *(float2*)&out[((size_t)(b * Co + co) * Ho + oh0 + ohl) * Wo + ow0 + owl] = o;
                }
                if (mout) {
                    u16* mp = mout + ((size_t)(b * Co + co) * MHp + oh0 + ohl + 1) * MWp
                              + ow0 + owl + 1;
                    mp[0] = f2h(fmaxf(v0, 0.f));
                    mp[1] = f2h(fmaxf(v1, 0.f));
                }
            }
        }
}

// ===========================================================================
// HMMA conv-transpose per-parity — fused mirror epilogue
// ===========================================================================

__global__ void __launch_bounds__(128, 2) tconv_tcf(
    const u32* __restrict__ mir, const u32* __restrict__ wT2,
    const float* __restrict__ bias, float* __restrict__ out,
    int Ci, int Co, int Hi, int Wi, int Hp, int Wp2, int w_shift, int relu_out,
    int wout, u16* __restrict__ mout, int MHp, int MWp)
{
    extern __shared__ u32 sm[];
    const int tid = threadIdx.x;
    const int lane = tid & 31, warp = tid >> 5;
    const int gid = lane >> 2, tig = lane & 3;
    const int m0w = (warp & 1) * 64, n0w = (warp >> 1) * 64;
    const int OWT = 1 << w_shift;
    const int ow0 = blockIdx.x * OWT, oh0 = blockIdx.y * (128 >> w_shift);
    const int p = blockIdx.z & 3;
    const int rest = blockIdx.z >> 2;
    const int cot = Co >> 7;
    const int b = rest / cot, c0 = (rest % cot) << 7;
    const int pa = p >> 1, pb = p & 1;
    const int K = Ci << 2, K2 = Ci << 1, NC = K >> 6;
    const int Ho = 2 * Hi, Wo2 = 2 * Wi;
    const u32* wTp = wT2 + (size_t)p * K2 * Co;
    const int sk = tid >> 2, sn0 = (tid & 3) << 5;
    const int mh = oh0 + (sn0 >> w_shift), mw = ow0 + (sn0 & (OWT - 1));
    const u32 sb = smem_u32(sm);

    auto stageA = [&](int c, int buf) {
        const int k02 = c << 5;
#pragma unroll
        for (int q = 0; q < 8; q++) {
            int idx = tid + (q << 7);
            int kk = idx >> 5, m4 = idx & 31;
            u32 dst = sb + ((u32)(buf * CHBUF + kk * 136 + (m4 << 2)) << 2);
            CP_A16(dst, wTp + (size_t)(k02 + kk) * Co + c0 + (m4 << 2));
        }
    };

    u32 us[17];
    auto loadB = [&](int c) {
        const int k = (c << 6) + 2 * sk;
        const int ci = k >> 2, j2 = k & 3;
        const int kh = (1 - pa) + 2 * (j2 >> 1);
        const int dm = (kh == 0) ? 1 : ((kh == 3) ? -1 : 0);
        const size_t base = ((size_t)(b * Ci + ci) * Hp + mh + dm + 1) * Wp2 + (mw >> 1);
        const uint4* q4 = (const uint4*)(mir + base);
#pragma unroll
        for (int i = 0; i < 4; i++) {
            uint4 v = q4[i];
            us[4 * i] = v.x; us[4 * i + 1] = v.y;
            us[4 * i + 2] = v.z; us[4 * i + 3] = v.w;
        }
        us[16] = mir[base + 16];
    };

    float acc[4][8][4];
#pragma unroll
    for (int mi = 0; mi < 4; mi++)
#pragma unroll
        for (int ni = 0; ni < 8; ni++)
#pragma unroll
            for (int c = 0; c < 4; c++) acc[mi][ni][c] = 0.f;

    stageA(0, 0);
    CP_COMMIT();
    loadB(0);

    for (int c = 0; c < NC; c++) {
        {
            u32* dst = sm + 2 * CHBUF + (c & 1) * CHBUF + sk * 136 + sn0;
            if (pb == 0) {
#pragma unroll
                for (int q = 0; q < 16; q++) {
                    u32 a = us[q], bb = us[q + 1];
                    dst[2 * q]     = prmt(a, a, 0x1032);
                    dst[2 * q + 1] = prmt(a, bb, 0x3254);
                }
            } else {
#pragma unroll
                for (int q = 0; q < 16; q++) {
                    u32 a = us[q], bb = us[q + 1];
                    dst[2 * q]     = prmt(a, bb, 0x3254);
                    dst[2 * q + 1] = prmt(bb, bb, 0x1032);
                }
            }
        }
        if (c + 1 < NC) { stageA(c + 1, (c + 1) & 1); CP_COMMIT(); CP_WAIT1(); }
        else CP_WAIT0();
        __syncthreads();
        if (c + 1 < NC) loadB(c + 1);

        const u32* As = sm + (c & 1) * CHBUF;
        const u32* Bs = sm + 2 * CHBUF + (c & 1) * CHBUF;
#pragma unroll
        for (int s = 0; s < 4; s++) {
            const int k2b = s * 8;
            u32 a[4][4], bf[8][2];
#pragma unroll
            for (int mi = 0; mi < 4; mi++) {
                a[mi][0] = As[(k2b + tig) * 136 + m0w + mi * 16 + gid];
                a[mi][1] = As[(k2b + tig) * 136 + m0w + mi * 16 + gid + 8];
                a[mi][2] = As[(k2b + tig + 4) * 136 + m0w + mi * 16 + gid];
                a[mi][3] = As[(k2b + tig + 4) * 136 + m0w + mi * 16 + gid + 8];
            }
#pragma unroll
            for (int ni = 0; ni < 8; ni++) {
                bf[ni][0] = Bs[(k2b + tig) * 136 + n0w + ni * 8 + gid];
                bf[ni][1] = Bs[(k2b + tig + 4) * 136 + n0w + ni * 8 + gid];
            }
#pragma unroll
            for (int mi = 0; mi < 4; mi++)
#pragma unroll
                for (int ni = 0; ni < 8; ni++)
                    MMA_F16(acc[mi][ni], a[mi][0], a[mi][1], a[mi][2], a[mi][3],
                            bf[ni][0], bf[ni][1]);
        }
        __syncthreads();
    }

#pragma unroll
    for (int mi = 0; mi < 4; mi++)
#pragma unroll
        for (int h = 0; h < 2; h++) {
            const int co = c0 + m0w + mi * 16 + gid + h * 8;
            const float bv = bias[co];
#pragma unroll
            for (int ni = 0; ni < 8; ni++) {
                const int n = n0w + ni * 8 + 2 * tig;
                const int mhh = oh0 + (n >> w_shift);
                const int mww = ow0 + (n & (OWT - 1));
                float v0 = acc[mi][ni][h * 2] + bv;
                float v1 = acc[mi][ni][h * 2 + 1] + bv;
                const int orow_i = 2 * mhh + pa;
                if (wout) {
                    float s0 = relu_out ? fmaxf(v0, 0.f) : v0;
                    float s1 = relu_out ? fmaxf(v1, 0.f) : v1;
                    float* orow = &out[((size_t)(b * Co + co) * Ho + orow_i) * Wo2];
                    orow[2 * mww + pb] = s0;
                    orow[2 * (mww + 1) + pb] = s1;
                }
                if (mout) {
                    u16* mp = mout + ((size_t)(b * Co + co) * MHp + orow_i + 1) * MWp;
                    mp[2 * mww + pb + 1] = f2h(fmaxf(v0, 0.f));
                    mp[2 * (mww + 1) + pb + 1] = f2h(fmaxf(v1, 0.f));
                }
            }
        }
}

// ===========================================================================
// HMMA 3x3 res conv — mirror-staged (proven)
// ===========================================================================

template <int O>
__device__ __forceinline__ void canon16(u32* w, const u32 (&us)[20], int p) {
    if (p) {
#pragma unroll
        for (int i = 0; i < 16; i++) w[i] = prmt(us[O + i], us[O + i + 1], 0x5432);
    } else {
#pragma unroll
        for (int i = 0; i < 16; i++) w[i] = us[O + i];
    }
}
__device__ __forceinline__ void canon(u32* w, const u32 (&us)[20], int o, int p) {
    switch (o) {
    case 0:  canon16<0>(w, us, p); break;
    case 1:  canon16<1>(w, us, p); break;
    case 2:  canon16<2>(w, us, p); break;
    default: canon16<3>(w, us, p); break;
    }
}

__global__ void __launch_bounds__(256, 2) conv3x3_tcf(
    const u32* __restrict__ mir, const u32* __restrict__ wT2,
    float* __restrict__ out, int Ci, int HW, int hw_shift, int Hp, int Wp2)
{
    __shared__ u32 A_s[32][40];
    __shared__ u32 B_s[32][264];
    const int tid = threadIdx.x;
    const int lane = tid & 31, warp = tid >> 5;
    const int gid = lane >> 2, tig = lane & 3;
    const int n0w = warp * 32;
    const int p0 = blockIdx.x * 256;
    const int b = blockIdx.z;
    const int K = Ci * 9;

    const int sk = tid >> 3;
    const int sn0 = (tid & 7) << 5;
    const int ng0 = p0 + sn0;
    const int s_oh = ng0 >> hw_shift;
    const int s_ow = ng0 & (HW - 1);

    float acc[2][4][4];
#pragma unroll
    for (int mi = 0; mi < 2; mi++)
#pragma unroll
        for (int ni = 0; ni < 4; ni++)
#pragma unroll
            for (int c = 0; c < 4; c++) acc[mi][ni][c] = 0.f;

    for (int k0 = 0; k0 < K; k0 += 64) {
        const int k02 = k0 >> 1;
        for (int idx = tid; idx < 1024; idx += 256) {
            int kk = idx >> 5, m = idx & 31;
            A_s[kk][m] = wT2[(size_t)(k02 + kk) * 32 + m];
        }
        {
            const int klo = k0 + 2 * sk, khi = klo + 1;
            const int ci0 = klo / 9, t0 = klo - ci0 * 9;
            const int ci1 = khi / 9, t1 = khi - ci1 * 9;
            const int kh0 = t0 / 3, kw0 = t0 - 3 * kh0;
            const int kh1 = t1 / 3, kw1 = t1 - 3 * kh1;
            const u32* r0 = mir + ((size_t)(b * Ci + ci0) * Hp + s_oh + kh0) * Wp2;
            const u32* r1 = mir + ((size_t)(b * Ci + ci1) * Hp + s_oh + kh1) * Wp2;
            const int h0 = s_ow + kw0, h1 = s_ow + kw1;
            const int b0i = h0 >> 1, b1i = h1 >> 1;
            const int al0 = b0i & ~3, al1 = b1i & ~3;
            u32 us0[20], us1[20], w0[16], w1[16];
            {
                const uint4* q4 = (const uint4*)(r0 + al0);
#pragma unroll
                for (int i = 0; i < 5; i++) {
                    uint4 v = q4[i];
                    us0[4 * i] = v.x; us0[4 * i + 1] = v.y;
                    us0[4 * i + 2] = v.z; us0[4 * i + 3] = v.w;
                }
            }
            canon(w0, us0, b0i - al0, h0 & 1);
            {
                const uint4* q4 = (const uint4*)(r1 + al1);
#pragma unroll
                for (int i = 0; i < 5; i++) {
                    uint4 v = q4[i];
                    us1[4 * i] = v.x; us1[4 * i + 1] = v.y;
                    us1[4 * i + 2] = v.z; us1[4 * i + 3] = v.w;
                }
            }
            canon(w1, us1, b1i - al1, h1 & 1);
            u32* dst = &B_s[sk][sn0];
#pragma unroll
            for (int t = 0; t < 8; t++) {
                uint4 o;
                o.x = prmt(w0[2 * t],     w1[2 * t],     0x5410);
                o.y = prmt(w0[2 * t],     w1[2 * t],     0x7632);
                o.z = prmt(w0[2 * t + 1], w1[2 * t + 1], 0x5410);
                o.w = prmt(w0[2 * t + 1], w1[2 * t + 1], 0x7632);
                *(uint4*)(dst + 4 * t) = o;
            }
        }
        __syncthreads();
#pragma unroll
        for (int s = 0; s < 4; s++) {
            const int k2b = s * 8;
            u32 a[2][4], bf[4][2];
#pragma unroll
            for (int mi = 0; mi < 2; mi++) {
                a[mi][0] = A_s[k2b + tig][mi * 16 + gid];
                a[mi][1] = A_s[k2b + tig][mi * 16 + gid + 8];
                a[mi][2] = A_s[k2b + tig + 4][mi * 16 + gid];
                a[mi][3] = A_s[k2b + tig + 4][mi * 16 + gid + 8];
            }
#pragma unroll
            for (int ni = 0; ni < 4; ni++) {
                bf[ni][0] = B_s[k2b + tig][n0w + ni * 8 + gid];
                bf[ni][1] = B_s[k2b + tig + 4][n0w + ni * 8 + gid];
            }
#pragma unroll
            for (int mi = 0; mi < 2; mi++)
#pragma unroll
                for (int ni = 0; ni < 4; ni++)
                    MMA_F16(acc[mi][ni], a[mi][0], a[mi][1], a[mi][2], a[mi][3],
                            bf[ni][0], bf[ni][1]);
        }
        __syncthreads();
    }

#pragma unroll
    for (int mi = 0; mi < 2; mi++)
#pragma unroll
        for (int h = 0; h < 2; h++) {
            const int co = mi * 16 + gid + h * 8;
#pragma unroll
            for (int ni = 0; ni < 4; ni++) {
                const int ng = p0 + n0w + ni * 8 + 2 * tig;
                const int oh = ng >> hw_shift, ow = ng & (HW - 1);
                float2 o = {acc[mi][ni][h * 2], acc[mi][ni][h * 2 + 1]};
                *(float2*)&out[((size_t)(b * 32 + co) * HW + oh) * HW + ow] = o;
            }
        }
}

// ===========================================================================
extern "C" void kernel_launch(void* const* d_in, const int* in_sizes, int n_in,
                              void* d_out, int out_size)
{
    (void)in_sizes; (void)n_in;
    const float* x       = (const float*)d_in[0];
    const float* enc_w1  = (const float*)d_in[1];
    const float* enc_b1  = (const float*)d_in[2];
    const float* enc_w2  = (const float*)d_in[3];
    const float* enc_b2  = (const float*)d_in[4];
    const float* enc_w3  = (const float*)d_in[5];
    const float* enc_b3  = (const float*)d_in[6];
    const float* enc_rw3 = (const float*)d_in[7];
    const float* enc_rw1 = (const float*)d_in[8];
    const float* prevq_w = (const float*)d_in[9];
    const float* prevq_b = (const float*)d_in[10];
    const float* emb     = (const float*)d_in[11];
    const float* dec_w1  = (const float*)d_in[12];
    const float* dec_b1  = (const float*)d_in[13];
    const float* dec_rw3 = (const float*)d_in[14];
    const float* dec_rw1 = (const float*)d_in[15];
    const float* dec_w2  = (const float*)d_in[16];
    const float* dec_b2  = (const float*)d_in[17];
    const float* dec_w3  = (const float*)d_in[18];
    const float* dec_b3  = (const float*)d_in[19];
    float* out = (float*)d_out;

    float *b0, *b1, *b2, *b3, *ze, *loss;
    u32 *wt, *mx, *m0, *m1, *me, *mq;
    cudaGetSymbolAddress((void**)&b0, g_b0);
    cudaGetSymbolAddress((void**)&b1, g_b1);
    cudaGetSymbolAddress((void**)&b2, g_b2);
    cudaGetSymbolAddress((void**)&b3, g_b3);
    cudaGetSymbolAddress((void**)&ze, g_ze);
    cudaGetSymbolAddress((void**)&loss, g_loss);
    cudaGetSymbolAddress((void**)&wt, g_wt);
    cudaGetSymbolAddress((void**)&mx, g_mx);
    cudaGetSymbolAddress((void**)&m0, g_m0);
    cudaGetSymbolAddress((void**)&m1, g_m1);
    cudaGetSymbolAddress((void**)&me, g_me);
    cudaGetSymbolAddress((void**)&mq, g_mq);

    const int DSM = 4 * CHBUF * 4;   // 69632 bytes
    cudaFuncSetAttribute(conv4s2_tcf, cudaFuncAttributeMaxDynamicSharedMemorySize, DSM);
    cudaFuncSetAttribute(tconv_tcf,   cudaFuncAttributeMaxDynamicSharedMemorySize, DSM);

    // ---- encoder ----
    cvt_mirror<<<dim3(134, 128), 256>>>(x, mx, 256, 256, 258, 132, 0, 3, 2);
    wt4s2_f16<<<16, 256>>>(enc_w1, wt, 4, 128, 3);
    conv4s2_tcf<<<dim3(1, 128, 32), 128, DSM>>>(mx, wt, enc_b1, nullptr,
        4, 128, 258, 132, 128, 128, 7, 1, 0, (u16*)m0, 130, 136);

    wt4s2_f16<<<1024, 256>>>(enc_w2, wt, 128, 256, 128);
    conv4s2_tcf<<<dim3(1, 32, 64), 128, DSM>>>(m0, wt, enc_b2, nullptr,
        128, 256, 130, 68, 64, 64, 6, 1, 0, (u16*)m1, 66, 72);

    wt4s2_f16<<<4096, 256>>>(enc_w3, wt, 256, 512, 256);
    conv4s2_tcf<<<dim3(1, 8, 128), 128, DSM>>>(m1, wt, enc_b3, b2,
        256, 512, 66, 36, 32, 32, 5, 0, 1, (u16*)me, 34, 40);

    wt3_f16<<<288, 256>>>(enc_rw3, wt, 512);
    for (int l = 0; l < 2; l++) {
        conv3x3_tcf<<<dim3(4, 1, 32), 256>>>(me, wt, b3, 512, 32, 5, 34, 20);
        conv1x1_kernel<<<dim3(16, 8, 32), 256>>>(b3, enc_rw1, nullptr, b2,
            32, 512, 1024, 1, 1, 1, l == 0 ? (u16*)me : nullptr, 34, 40, 5, 31);
    }
    conv1x1_kernel<<<dim3(16, 1, 32), 256>>>(b2, prevq_w, prevq_b, ze,
        512, 64, 1024, 1, 0, 1, nullptr, 0, 0, 5, 31);

    // ---- VQ ----
    zero_loss_kernel<<<1, 1>>>(loss);
    vq_kernel<<<128, 256>>>(ze, emb, (u16*)mq, loss);
    finish_loss_kernel<<<1, 1>>>(loss, out + (out_size - 1));

    // ---- decoder ----
    wtT_f16<<<512, 256>>>(dec_w1, wt, 64, 256);
    tconv_tcf<<<dim3(1, 8, 256), 128, DSM>>>(mq, wt, dec_b1, b1,
        64, 256, 32, 32, 34, 20, 5, 0, 1, (u16*)m1, 66, 72);

    wt3_f16<<<144, 256>>>(dec_rw3, wt, 256);
    for (int l = 0; l < 2; l++) {
        conv3x3_tcf<<<dim3(16, 1, 32), 256>>>(m1, wt, b3, 256, 64, 6, 66, 36);
        conv1x1_kernel<<<dim3(64, 4, 32), 256>>>(b3, dec_rw1, nullptr, b1,
            32, 256, 4096, 1, 1, l == 0 ? 1 : 0, (u16*)m1, 66, 72, 6, 63);
    }

    wtT_f16<<<1024, 256>>>(dec_w2, wt, 256, 128);
    tconv_tcf<<<dim3(1, 32, 128), 128, DSM>>>(m1, wt, dec_b2, nullptr,
        256, 128, 64, 64, 66, 36, 6, 1, 0, (u16*)m0, 130, 136);

    tconv3_f32<<<dim3(8, 8, 32), 256>>>((const u16*)m0, dec_w3, dec_b3, out);
}

// round 15
// speedup vs baseline: 1.0255x; 1.0255x over previous
#include <cuda_runtime.h>

typedef unsigned int u32;
typedef unsigned short u16;

__device__ float g_b0[32u * 128 * 128 * 128];
__device__ float g_b1[32u * 256 * 64 * 64];
__device__ float g_b2[32u * 512 * 32 * 32];
__device__ float g_b3[32u * 32 * 64 * 64];
__device__ float g_ze[32u * 64 * 32 * 32];
__device__ float g_loss[1];
__device__ u32   g_wt[2097152];
__device__ u32   g_mx[4359168];    // enc1 in: 128 x 258 x 132 u32
__device__ u32   g_m0[36218880];   // enc2 in: 4096 x 130 x 68 u32
__device__ u32   g_m1[19464192];   // enc3-in / dec-res / dec2-in: 8192 x 66 x 36
__device__ u32   g_me[11141120];   // enc-res: 16384 x 34 x 20 u32
__device__ u32   g_mq[1392640];    // dec1 in: 2048 x 34 x 20 u32

__device__ __forceinline__ u32 pack_f16x2(float lo, float hi) {
    u32 r; asm("cvt.rn.f16x2.f32 %0,%1,%2;" : "=r"(r) : "f"(hi), "f"(lo)); return r;
}
__device__ __forceinline__ u16 f2h(float f) {
    u16 h; asm("cvt.rn.f16.f32 %0,%1;" : "=h"(h) : "f"(f)); return h;
}
__device__ __forceinline__ u32 prmt(u32 a, u32 b, u32 s) {
    u32 r; asm("prmt.b32 %0,%1,%2,%3;" : "=r"(r) : "r"(a), "r"(b), "r"(s)); return r;
}
__device__ __forceinline__ u32 smem_u32(const void* p) {
    u32 a; asm("{ .reg .u64 t; cvta.to.shared.u64 t,%1; cvt.u32.u64 %0,t; }"
               : "=r"(a) : "l"(p));
    return a;
}

#define CP_A16(d, s) asm volatile("cp.async.ca.shared.global [%0],[%1],16;" :: "r"(d), "l"(s))
#define CP_A4(d, s)  asm volatile("cp.async.ca.shared.global [%0],[%1],4;"  :: "r"(d), "l"(s))
#define CP_COMMIT()  asm volatile("cp.async.commit_group;" ::: "memory")
#define CP_WAIT0()   asm volatile("cp.async.wait_group 0;" ::: "memory")
#define CP_WAIT1()   asm volatile("cp.async.wait_group 1;" ::: "memory")

#define MMA_F16(d, a0, a1, a2, a3, b0, b1)                                    \
    asm volatile("mma.sync.aligned.m16n8k16.row.col.f32.f16.f16.f32 "         \
                 "{%0,%1,%2,%3},{%4,%5,%6,%7},{%8,%9},{%0,%1,%2,%3};"         \
                 : "+f"(d[0]), "+f"(d[1]), "+f"(d[2]), "+f"(d[3])             \
                 : "r"(a0), "r"(a1), "r"(a2), "r"(a3), "r"(b0), "r"(b1))

// ---- mirror build (network input only) -------------------------------------
__global__ void cvt_mirror(const float* __restrict__ src, u32* __restrict__ dst,
                           int Hi, int Wi, int Hp, int Wp2, int relu,
                           int scpb, int dshift)
{
    const int plane = blockIdx.y;
    const int idx = blockIdx.x * 256 + threadIdx.x;
    if (idx >= Hp * Wp2) return;
    const int ph = idx / Wp2, wp2 = idx - ph * Wp2;
    const int b = plane >> dshift;
    const int c = plane & ((1 << dshift) - 1);
    const int ih = ph - 1;
    const int iw0 = 2 * wp2 - 1, iw1 = iw0 + 1;
    float v0 = 0.f, v1 = 0.f;
    if (c < scpb && (unsigned)ih < (unsigned)Hi) {
        const float* r = src + ((size_t)(b * scpb + c) * Hi + ih) * Wi;
        if ((unsigned)iw0 < (unsigned)Wi) v0 = r[iw0];
        if ((unsigned)iw1 < (unsigned)Wi) v1 = r[iw1];
    }
    if (relu) { v0 = fmaxf(v0, 0.f); v1 = fmaxf(v1, 0.f); }
    dst[(size_t)plane * Hp * Wp2 + idx] = pack_f16x2(v0, v1);
}

// ===========================================================================
// conv1x1 fp32 — optional fused mirror output
// ===========================================================================

__global__ void __launch_bounds__(256) conv1x1_kernel(
    const float* __restrict__ in, const float* __restrict__ w,
    const float* __restrict__ bias, float* __restrict__ out,
    int Ci, int Co, int P, int relu_in, int add_res,
    int wout, u16* __restrict__ mout, int MHp, int MWp, int hw_shift, int hwm)
{
    __shared__ float w_s[16][64];
    __shared__ float x_s[16][64];
    const int tid = threadIdx.x;
    const int tx = tid & 15, ty = tid >> 4;
    const int p0 = blockIdx.x * 64, c0 = blockIdx.y * 64, b = blockIdx.z;

    float acc[4][4];
#pragma unroll
    for (int i = 0; i < 4; i++)
#pragma unroll
        for (int j = 0; j < 4; j++) acc[i][j] = 0.f;

    for (int ci0 = 0; ci0 < Ci; ci0 += 16) {
        for (int idx = tid; idx < 1024; idx += 256) {
            int p = idx & 63, ci = idx >> 6;
            float v = in[(size_t)(b * Ci + ci0 + ci) * P + p0 + p];
            x_s[ci][p] = relu_in ? fmaxf(v, 0.f) : v;
        }
        for (int idx = tid; idx < 1024; idx += 256) {
            int ci = idx & 15, co = idx >> 4;
            w_s[ci][co] = w[(size_t)(c0 + co) * Ci + ci0 + ci];
        }
        __syncthreads();
#pragma unroll
        for (int ci = 0; ci < 16; ci++) {
            const float4 wv = *(const float4*)&w_s[ci][ty << 2];
            const float4 xv = *(const float4*)&x_s[ci][tx << 2];
            const float wvv[4] = {wv.x, wv.y, wv.z, wv.w};
            const float xvv[4] = {xv.x, xv.y, xv.z, xv.w};
#pragma unroll
            for (int i = 0; i < 4; i++)
#pragma unroll
                for (int j = 0; j < 4; j++)
                    acc[i][j] = fmaf(wvv[i], xvv[j], acc[i][j]);
        }
        __syncthreads();
    }
#pragma unroll
    for (int i = 0; i < 4; i++) {
        const int co = c0 + (ty << 2) + i;
        const float bv = bias ? bias[co] : 0.f;
        const int px = p0 + (tx << 2);
        const size_t base = (size_t)(b * Co + co) * P + px;
        float4 o = {acc[i][0] + bv, acc[i][1] + bv, acc[i][2] + bv, acc[i][3] + bv};
        if (add_res) {
            float4 rr = *(const float4*)&out[base];
            o.x += rr.x; o.y += rr.y; o.z += rr.z; o.w += rr.w;
        }
        if (wout) *(float4*)&out[base] = o;
        if (mout) {
            const int oh = px >> hw_shift, ow = px & hwm;
            u16* mp = mout + ((size_t)(b * Co + co) * MHp + oh + 1) * MWp + ow + 1;
            mp[0] = f2h(fmaxf(o.x, 0.f));
            mp[1] = f2h(fmaxf(o.y, 0.f));
            mp[2] = f2h(fmaxf(o.z, 0.f));
            mp[3] = f2h(fmaxf(o.w, 0.f));
        }
    }
}

// ===========================================================================
// VQ — writes dec1 mirror directly (256 blocks x 128 threads)
// ===========================================================================

__global__ void __launch_bounds__(128) vq_kernel(
    const float* __restrict__ ze, const float* __restrict__ emb,
    u16* __restrict__ mq, float* __restrict__ loss)
{
    __shared__ float e_s[128 * 64];
    __shared__ float n_s[128];
    const int tid = threadIdx.x;
    const int n = blockIdx.x * 128 + tid;
    const int b = n >> 10, hw = n & 1023;

    float xr[64];
#pragma unroll
    for (int d = 0; d < 64; d++)
        xr[d] = ze[((size_t)(b * 64 + d) << 10) + hw];

    float best = 3.4e38f;
    int bi = 0;
    for (int kb = 0; kb < 4; kb++) {
        __syncthreads();
        for (int i = tid; i < 128 * 64; i += 128) e_s[i] = emb[kb * 128 * 64 + i];
        __syncthreads();
        {
            float s = 0.f;
#pragma unroll 8
            for (int d = 0; d < 64; d++) { float v = e_s[tid * 64 + d]; s = fmaf(v, v, s); }
            n_s[tid] = s;
        }
        __syncthreads();
        for (int k = 0; k < 128; k++) {
            const float4* e4 = (const float4*)(e_s + k * 64);
            float dot = 0.f;
#pragma unroll
            for (int d4 = 0; d4 < 16; d4++) {
                float4 e = e4[d4];
                dot = fmaf(e.x, xr[d4 * 4 + 0], dot);
                dot = fmaf(e.y, xr[d4 * 4 + 1], dot);
                dot = fmaf(e.z, xr[d4 * 4 + 2], dot);
                dot = fmaf(e.w, xr[d4 * 4 + 3], dot);
            }
            float dist = n_s[k] - 2.f * dot;
            if (dist < best) { best = dist; bi = kb * 128 + k; }
        }
    }

    const int oh = hw >> 5, ow = hw & 31;
    float ls = 0.f;
#pragma unroll
    for (int d = 0; d < 64; d++) {
        float e = emb[bi * 64 + d];
        mq[((size_t)(b * 64 + d) * 34 + oh + 1) * 40 + ow + 1] = f2h(e);
        float df = e - xr[d];
        ls = fmaf(df, df, ls);
    }
#pragma unroll
    for (int o = 16; o > 0; o >>= 1) ls += __shfl_down_sync(0xffffffffu, ls, o);
    if ((tid & 31) == 0) atomicAdd(loss, ls);
}

// fp32 tconv for dec3 (proven)
template <int CO_TILE, int CO_PT, int M_TILE, int N_TILE>
__global__ void __launch_bounds__(256) tconv_kernel(
    const float* __restrict__ in, const float* __restrict__ w,
    const float* __restrict__ bias, float* __restrict__ out,
    int Ci, int Co, int Hi, int Wi, int relu_in, int relu_out)
{
    constexpr int NSLOT = (M_TILE * N_TILE) / 4;
    constexpr int CG = CO_TILE / CO_PT;
    static_assert(NSLOT * CG == 256, "map");
    __shared__ float w_s[4][16][CO_TILE];
    __shared__ float x_s[4][M_TILE + 2][N_TILE + 2];

    const int tid = threadIdx.x;
    const int slot = tid % NSLOT, cg = tid / NSLOT;
    const int m_loc = slot / (N_TILE / 4);
    const int nb = (slot % (N_TILE / 4)) * 4;
    const int n0 = blockIdx.x * N_TILE, m0 = blockIdx.y * M_TILE;
    const int cot = (Co + CO_TILE - 1) / CO_TILE;
    const int b = blockIdx.z / cot, c0 = (blockIdx.z % cot) * CO_TILE;
    const int Ho = 2 * Hi, Wo2 = 2 * Wi;

    float acc[CO_PT][4][2][2];
#pragma unroll
    for (int i = 0; i < CO_PT; i++)
#pragma unroll
        for (int q = 0; q < 4; q++)
#pragma unroll
            for (int a = 0; a < 2; a++)
#pragma unroll
                for (int bb = 0; bb < 2; bb++) acc[i][q][a][bb] = 0.f;

    for (int ci0 = 0; ci0 < Ci; ci0 += 4) {
        for (int idx = tid; idx < 4 * (M_TILE + 2) * (N_TILE + 2); idx += 256) {
            int lc = idx % (N_TILE + 2);
            int t = idx / (N_TILE + 2);
            int lr = t % (M_TILE + 2), ci = t / (M_TILE + 2);
            int m = m0 - 1 + lr, nn = n0 - 1 + lc;
            float v = 0.f;
            if ((unsigned)m < (unsigned)Hi && (unsigned)nn < (unsigned)Wi)
                v = in[((size_t)(b * Ci + ci0 + ci) * Hi + m) * Wi + nn];
            if (relu_in) v = fmaxf(v, 0.f);
            x_s[ci][lr][lc] = v;
        }
        for (int idx = tid; idx < 4 * 16 * CO_TILE; idx += 256) {
            int t = idx & 15;
            int co = (idx >> 4) % CO_TILE;
            int ci = idx / (16 * CO_TILE);
            float v = 0.f;
            if (c0 + co < Co) v = w[((size_t)(ci0 + ci) * Co + c0 + co) * 16 + t];
            w_s[ci][t][co] = v;
        }
        __syncthreads();
#pragma unroll
        for (int ci = 0; ci < 4; ci++)
#pragma unroll
            for (int t = 0; t < 16; t++) {
                const int kh = t >> 2, kw = t & 3;
                const int a = 1 - (kh & 1);
                const int dm = (kh == 0) ? 1 : ((kh == 3) ? -1 : 0);
                const int bb = 1 - (kw & 1);
                const int dn = (kw == 0) ? 1 : ((kw == 3) ? -1 : 0);
                float wr[CO_PT];
#pragma unroll
                for (int i = 0; i < CO_PT; i++)
                    wr[i] = w_s[ci][t][cg * CO_PT + i];
                const float* xrow = &x_s[ci][m_loc + dm + 1][nb + dn + 1];
#pragma unroll
                for (int q = 0; q < 4; q++) {
                    const float xv = xrow[q];
#pragma unroll
                    for (int i = 0; i < CO_PT; i++)
                        acc[i][q][a][bb] = fmaf(wr[i], xv, acc[i][q][a][bb]);
                }
            }
        __syncthreads();
    }

    const int m = m0 + m_loc;
#pragma unroll
    for (int i = 0; i < CO_PT; i++) {
        const int co = c0 + cg * CO_PT + i;
        if (co < Co) {
            const float bv = bias[co];
#pragma unroll
            for (int q = 0; q < 4; q++) {
                const int nn = n0 + nb + q;
#pragma unroll
                for (int a = 0; a < 2; a++) {
                    float2 o = {acc[i][q][a][0] + bv, acc[i][q][a][1] + bv};
                    if (relu_out) { o.x = fmaxf(o.x, 0.f); o.y = fmaxf(o.y, 0.f); }
                    *(float2*)&out[((size_t)(b * Co + co) * Ho + 2 * m + a) * Wo2 + 2 * nn] = o;
                }
            }
        }
    }
}

__global__ void zero_loss_kernel(float* loss) { loss[0] = 0.f; }
__global__ void finish_loss_kernel(const float* __restrict__ loss, float* __restrict__ dst)
{
    dst[0] = 2.f * loss[0] / 2097152.f;
}

// ===========================================================================
// weight prepacks (fp16)
// ===========================================================================

__global__ void wt4s2_f16(const float* __restrict__ w, u32* __restrict__ wT2,
                          int Ci, int Co, int Ci_src)
{
    int idx = blockIdx.x * 256 + threadIdx.x;
    if (idx >= Ci * 8 * Co) return;
    int co = idx % Co, k2 = idx / Co;
    int k = 2 * k2, ci = k >> 4, t = k & 15;
    float v0 = 0.f, v1 = 0.f;
    if (ci < Ci_src) {
        const float* base = &w[((size_t)co * Ci_src + ci) * 16 + t];
        v0 = base[0]; v1 = base[1];
    }
    wT2[idx] = pack_f16x2(v0, v1);
}

__global__ void wtT_f16(const float* __restrict__ w, u32* __restrict__ wT2,
                        int Ci, int Co)
{
    int K2 = Ci * 2;
    int idx = blockIdx.x * 256 + threadIdx.x;
    if (idx >= 4 * K2 * Co) return;
    int co = idx % Co, rr = idx / Co;
    int p = rr / K2, k2 = rr % K2;
    int k = 2 * k2, ci = k >> 2, j = k & 3;
    int a = p >> 1, bb = p & 1;
    int kh = (1 - a) + 2 * (j >> 1);
    const float* base = &w[((size_t)ci * Co + co) * 16 + kh * 4];
    wT2[idx] = pack_f16x2(base[1 - bb], base[3 - bb]);
}

__global__ void wt3_f16(const float* __restrict__ w, u32* __restrict__ wT2, int Ci)
{
    int K = Ci * 9;
    int idx = blockIdx.x * 256 + threadIdx.x;
    if (idx >= (K / 2) * 32) return;
    int co = idx & 31, k2 = idx >> 5;
    int k0 = 2 * k2, k1 = k0 + 1;
    int ci0 = k0 / 9, t0 = k0 - ci0 * 9;
    int ci1 = k1 / 9, t1 = k1 - ci1 * 9;
    wT2[idx] = pack_f16x2(w[((size_t)co * Ci + ci0) * 9 + t0],
                          w[((size_t)co * Ci + ci1) * 9 + t1]);
}

// ===========================================================================
// HMMA conv k4 s2 p1 — fused mirror epilogue
// ===========================================================================

#define CHBUF 4352

__global__ void __launch_bounds__(128, 2) conv4s2_tcf(
    const u32* __restrict__ mir, const u32* __restrict__ wT2,
    const float* __restrict__ bias, float* __restrict__ out,
    int Ci, int Co, int Hp, int Wp2, int Ho, int Wo, int w_shift, int relu,
    int wout, u16* __restrict__ mout, int MHp, int MWp)
{
    extern __shared__ u32 sm[];
    const int tid = threadIdx.x;
    const int lane = tid & 31, warp = tid >> 5;
    const int gid = lane >> 2, tig = lane & 3;
    const int m0w = (warp & 1) * 64, n0w = (warp >> 1) * 64;
    const int OWT = 1 << w_shift;
    const int ow0 = blockIdx.x * OWT, oh0 = blockIdx.y * (128 >> w_shift);
    const int cot = Co >> 7;
    const int b = blockIdx.z / cot, c0 = (blockIdx.z % cot) << 7;
    const int K = Ci << 4, NC = K >> 6;
    const int sk = tid >> 2, sn0 = (tid & 3) << 5;
    const int oh = oh0 + (sn0 >> w_shift), ow = ow0 + (sn0 & (OWT - 1));
    const u32 sb = smem_u32(sm);

    auto stage = [&](int c, int buf) {
        const int k02 = c << 5;
#pragma unroll
        for (int q = 0; q < 8; q++) {
            int idx = tid + (q << 7);
            int kk = idx >> 5, m4 = idx & 31;
            u32 dst = sb + ((u32)(buf * CHBUF + kk * 136 + (m4 << 2)) << 2);
            CP_A16(dst, wT2 + (size_t)(k02 + kk) * Co + c0 + (m4 << 2));
        }
        const int k = (c << 6) + 2 * sk;
        const int ci = k >> 4, t = k & 15, kh = t >> 2, a1 = (t & 3) >> 1;
        const u32* src = mir + ((size_t)(b * Ci + ci) * Hp + 2 * oh + kh) * Wp2 + ow + a1;
        u32 dst = sb + ((u32)(2 * CHBUF + buf * CHBUF + sk * 136 + sn0) << 2);
        if (!a1) {
#pragma unroll
            for (int j = 0; j < 8; j++) CP_A16(dst + 16 * j, src + 4 * j);
        } else {
#pragma unroll
            for (int j = 0; j < 32; j++) CP_A4(dst + 4 * j, src + j);
        }
    };

    float acc[4][8][4];
#pragma unroll
    for (int mi = 0; mi < 4; mi++)
#pragma unroll
        for (int ni = 0; ni < 8; ni++)
#pragma unroll
            for (int c = 0; c < 4; c++) acc[mi][ni][c] = 0.f;

    stage(0, 0);
    CP_COMMIT();

    for (int c = 0; c < NC; c++) {
        if (c + 1 < NC) { stage(c + 1, (c + 1) & 1); CP_COMMIT(); CP_WAIT1(); }
        else CP_WAIT0();
        __syncthreads();
        const u32* As = sm + (c & 1) * CHBUF;
        const u32* Bs = sm + 2 * CHBUF + (c & 1) * CHBUF;
#pragma unroll
        for (int s = 0; s < 4; s++) {
            const int k2b = s * 8;
            u32 a[4][4], bf[8][2];
#pragma unroll
            for (int mi = 0; mi < 4; mi++) {
                a[mi][0] = As[(k2b + tig) * 136 + m0w + mi * 16 + gid];
                a[mi][1] = As[(k2b + tig) * 136 + m0w + mi * 16 + gid + 8];
                a[mi][2] = As[(k2b + tig + 4) * 136 + m0w + mi * 16 + gid];
                a[mi][3] = As[(k2b + tig + 4) * 136 + m0w + mi * 16 + gid + 8];
            }
#pragma unroll
            for (int ni = 0; ni < 8; ni++) {
                bf[ni][0] = Bs[(k2b + tig) * 136 + n0w + ni * 8 + gid];
                bf[ni][1] = Bs[(k2b + tig + 4) * 136 + n0w + ni * 8 + gid];
            }
#pragma unroll
            for (int mi = 0; mi < 4; mi++)
#pragma unroll
                for (int ni = 0; ni < 8; ni++)
                    MMA_F16(acc[mi][ni], a[mi][0], a[mi][1], a[mi][2], a[mi][3],
                            bf[ni][0], bf[ni][1]);
        }
        __syncthreads();
    }

#pragma unroll
    for (int mi = 0; mi < 4; mi++)
#pragma unroll
        for (int h = 0; h < 2; h++) {
            const int co = c0 + m0w + mi * 16 + gid + h * 8;
            const float bv = bias[co];
#pragma unroll
            for (int ni = 0; ni < 8; ni++) {
                const int n = n0w + ni * 8 + 2 * tig;
                const int ohl = n >> w_shift, owl = n & (OWT - 1);
                float v0 = acc[mi][ni][h * 2] + bv;
                float v1 = acc[mi][ni][h * 2 + 1] + bv;
                if (wout) {
                    float2 o = {relu ? fmaxf(v0, 0.f) : v0, relu ? fmaxf(v1, 0.f) : v1};
                    *(float2*)&out[((size_t)(b * Co + co) * Ho + oh0 + ohl) * Wo + ow0 + owl] = o;
                }
                if (mout) {
                    u16* mp = mout + ((size_t)(b * Co + co) * MHp + oh0 + ohl + 1) * MWp
                              + ow0 + owl + 1;
                    mp[0] = f2h(fmaxf(v0, 0.f));
                    mp[1] = f2h(fmaxf(v1, 0.f));
                }
            }
        }
}

// ===========================================================================
// HMMA conv-transpose per-parity — fused mirror epilogue
// ===========================================================================

__global__ void __launch_bounds__(128, 2) tconv_tcf(
    const u32* __restrict__ mir, const u32* __restrict__ wT2,
    const float* __restrict__ bias, float* __restrict__ out,
    int Ci, int Co, int Hi, int Wi, int Hp, int Wp2, int w_shift, int relu_out,
    int wout, u16* __restrict__ mout, int MHp, int MWp)
{
    extern __shared__ u32 sm[];
    const int tid = threadIdx.x;
    const int lane = tid & 31, warp = tid >> 5;
    const int gid = lane >> 2, tig = lane & 3;
    const int m0w = (warp & 1) * 64, n0w = (warp >> 1) * 64;
    const int OWT = 1 << w_shift;
    const int ow0 = blockIdx.x * OWT, oh0 = blockIdx.y * (128 >> w_shift);
    const int p = blockIdx.z & 3;
    const int rest = blockIdx.z >> 2;
    const int cot = Co >> 7;
    const int b = rest / cot, c0 = (rest % cot) << 7;
    const int pa = p >> 1, pb = p & 1;
    const int K = Ci << 2, K2 = Ci << 1, NC = K >> 6;
    const int Ho = 2 * Hi, Wo2 = 2 * Wi;
    const u32* wTp = wT2 + (size_t)p * K2 * Co;
    const int sk = tid >> 2, sn0 = (tid & 3) << 5;
    const int mh = oh0 + (sn0 >> w_shift), mw = ow0 + (sn0 & (OWT - 1));
    const u32 sb = smem_u32(sm);

    auto stageA = [&](int c, int buf) {
        const int k02 = c << 5;
#pragma unroll
        for (int q = 0; q < 8; q++) {
            int idx = tid + (q << 7);
            int kk = idx >> 5, m4 = idx & 31;
            u32 dst = sb + ((u32)(buf * CHBUF + kk * 136 + (m4 << 2)) << 2);
            CP_A16(dst, wTp + (size_t)(k02 + kk) * Co + c0 + (m4 << 2));
        }
    };

    u32 us[17];
    auto loadB = [&](int c) {
        const int k = (c << 6) + 2 * sk;
        const int ci = k >> 2, j2 = k & 3;
        const int kh = (1 - pa) + 2 * (j2 >> 1);
        const int dm = (kh == 0) ? 1 : ((kh == 3) ? -1 : 0);
        const size_t base = ((size_t)(b * Ci + ci) * Hp + mh + dm + 1) * Wp2 + (mw >> 1);
        const uint4* q4 = (const uint4*)(mir + base);
#pragma unroll
        for (int i = 0; i < 4; i++) {
            uint4 v = q4[i];
            us[4 * i] = v.x; us[4 * i + 1] = v.y;
            us[4 * i + 2] = v.z; us[4 * i + 3] = v.w;
        }
        us[16] = mir[base + 16];
    };

    float acc[4][8][4];
#pragma unroll
    for (int mi = 0; mi < 4; mi++)
#pragma unroll
        for (int ni = 0; ni < 8; ni++)
#pragma unroll
            for (int c = 0; c < 4; c++) acc[mi][ni][c] = 0.f;

    stageA(0, 0);
    CP_COMMIT();
    loadB(0);

    for (int c = 0; c < NC; c++) {
        {
            u32* dst = sm + 2 * CHBUF + (c & 1) * CHBUF + sk * 136 + sn0;
            if (pb == 0) {
#pragma unroll
                for (int q = 0; q < 16; q++) {
                    u32 a = us[q], bb = us[q + 1];
                    dst[2 * q]     = prmt(a, a, 0x1032);
                    dst[2 * q + 1] = prmt(a, bb, 0x3254);
                }
            } else {
#pragma unroll
                for (int q = 0; q < 16; q++) {
                    u32 a = us[q], bb = us[q + 1];
                    dst[2 * q]     = prmt(a, bb, 0x3254);
                    dst[2 * q + 1] = prmt(bb, bb, 0x1032);
                }
            }
        }
        if (c + 1 < NC) { stageA(c + 1, (c + 1) & 1); CP_COMMIT(); CP_WAIT1(); }
        else CP_WAIT0();
        __syncthreads();
        if (c + 1 < NC) loadB(c + 1);

        const u32* As = sm + (c & 1) * CHBUF;
        const u32* Bs = sm + 2 * CHBUF + (c & 1) * CHBUF;
#pragma unroll
        for (int s = 0; s < 4; s++) {
            const int k2b = s * 8;
            u32 a[4][4], bf[8][2];
#pragma unroll
            for (int mi = 0; mi < 4; mi++) {
                a[mi][0] = As[(k2b + tig) * 136 + m0w + mi * 16 + gid];
                a[mi][1] = As[(k2b + tig) * 136 + m0w + mi * 16 + gid + 8];
                a[mi][2] = As[(k2b + tig + 4) * 136 + m0w + mi * 16 + gid];
                a[mi][3] = As[(k2b + tig + 4) * 136 + m0w + mi * 16 + gid + 8];
            }
#pragma unroll
            for (int ni = 0; ni < 8; ni++) {
                bf[ni][0] = Bs[(k2b + tig) * 136 + n0w + ni * 8 + gid];
                bf[ni][1] = Bs[(k2b + tig + 4) * 136 + n0w + ni * 8 + gid];
            }
#pragma unroll
            for (int mi = 0; mi < 4; mi++)
#pragma unroll
                for (int ni = 0; ni < 8; ni++)
                    MMA_F16(acc[mi][ni], a[mi][0], a[mi][1], a[mi][2], a[mi][3],
                            bf[ni][0], bf[ni][1]);
        }
        __syncthreads();
    }

#pragma unroll
    for (int mi = 0; mi < 4; mi++)
#pragma unroll
        for (int h = 0; h < 2; h++) {
            const int co = c0 + m0w + mi * 16 + gid + h * 8;
            const float bv = bias[co];
#pragma unroll
            for (int ni = 0; ni < 8; ni++) {
                const int n = n0w + ni * 8 + 2 * tig;
                const int mhh = oh0 + (n >> w_shift);
                const int mww = ow0 + (n & (OWT - 1));
                float v0 = acc[mi][ni][h * 2] + bv;
                float v1 = acc[mi][ni][h * 2 + 1] + bv;
                const int orow_i = 2 * mhh + pa;
                if (wout) {
                    float s0 = relu_out ? fmaxf(v0, 0.f) : v0;
                    float s1 = relu_out ? fmaxf(v1, 0.f) : v1;
                    float* orow = &out[((size_t)(b * Co + co) * Ho + orow_i) * Wo2];
                    orow[2 * mww + pb] = s0;
                    orow[2 * (mww + 1) + pb] = s1;
                }
                if (mout) {
                    u16* mp = mout + ((size_t)(b * Co + co) * MHp + orow_i + 1) * MWp;
                    mp[2 * mww + pb + 1] = f2h(fmaxf(v0, 0.f));
                    mp[2 * (mww + 1) + pb + 1] = f2h(fmaxf(v1, 0.f));
                }
            }
        }
}

// ===========================================================================
// HMMA 3x3 res conv — mirror-staged (proven)
// ===========================================================================

template <int O>
__device__ __forceinline__ void canon16(u32* w, const u32 (&us)[20], int p) {
    if (p) {
#pragma unroll
        for (int i = 0; i < 16; i++) w[i] = prmt(us[O + i], us[O + i + 1], 0x5432);
    } else {
#pragma unroll
        for (int i = 0; i < 16; i++) w[i] = us[O + i];
    }
}
__device__ __forceinline__ void canon(u32* w, const u32 (&us)[20], int o, int p) {
    switch (o) {
    case 0:  canon16<0>(w, us, p); break;
    case 1:  canon16<1>(w, us, p); break;
    case 2:  canon16<2>(w, us, p); break;
    default: canon16<3>(w, us, p); break;
    }
}

__global__ void __launch_bounds__(256, 2) conv3x3_tcf(
    const u32* __restrict__ mir, const u32* __restrict__ wT2,
    float* __restrict__ out, int Ci, int HW, int hw_shift, int Hp, int Wp2)
{
    __shared__ u32 A_s[32][40];
    __shared__ u32 B_s[32][264];
    const int tid = threadIdx.x;
    const int lane = tid & 31, warp = tid >> 5;
    const int gid = lane >> 2, tig = lane & 3;
    const int n0w = warp * 32;
    const int p0 = blockIdx.x * 256;
    const int b = blockIdx.z;
    const int K = Ci * 9;

    const int sk = tid >> 3;
    const int sn0 = (tid & 7) << 5;
    const int ng0 = p0 + sn0;
    const int s_oh = ng0 >> hw_shift;
    const int s_ow = ng0 & (HW - 1);

    float acc[2][4][4];
#pragma unroll
    for (int mi = 0; mi < 2; mi++)
#pragma unroll
        for (int ni = 0; ni < 4; ni++)
#pragma unroll
            for (int c = 0; c < 4; c++) acc[mi][ni][c] = 0.f;

    for (int k0 = 0; k0 < K; k0 += 64) {
        const int k02 = k0 >> 1;
        for (int idx = tid; idx < 1024; idx += 256) {
            int kk = idx >> 5, m = idx & 31;
            A_s[kk][m] = wT2[(size_t)(k02 + kk) * 32 + m];
        }
        {
            const int klo = k0 + 2 * sk, khi = klo + 1;
            const int ci0 = klo / 9, t0 = klo - ci0 * 9;
            const int ci1 = khi / 9, t1 = khi - ci1 * 9;
            const int kh0 = t0 / 3, kw0 = t0 - 3 * kh0;
            const int kh1 = t1 / 3, kw1 = t1 - 3 * kh1;
            const u32* r0 = mir + ((size_t)(b * Ci + ci0) * Hp + s_oh + kh0) * Wp2;
            const u32* r1 = mir + ((size_t)(b * Ci + ci1) * Hp + s_oh + kh1) * Wp2;
            const int h0 = s_ow + kw0, h1 = s_ow + kw1;
            const int b0i = h0 >> 1, b1i = h1 >> 1;
            const int al0 = b0i & ~3, al1 = b1i & ~3;
            u32 us0[20], us1[20], w0[16], w1[16];
            {
                const uint4* q4 = (const uint4*)(r0 + al0);
#pragma unroll
                for (int i = 0; i < 5; i++) {
                    uint4 v = q4[i];
                    us0[4 * i] = v.x; us0[4 * i + 1] = v.y;
                    us0[4 * i + 2] = v.z; us0[4 * i + 3] = v.w;
                }
            }
            canon(w0, us0, b0i - al0, h0 & 1);
            {
                const uint4* q4 = (const uint4*)(r1 + al1);
#pragma unroll
                for (int i = 0; i < 5; i++) {
                    uint4 v = q4[i];
                    us1[4 * i] = v.x; us1[4 * i + 1] = v.y;
                    us1[4 * i + 2] = v.z; us1[4 * i + 3] = v.w;
                }
            }
            canon(w1, us1, b1i - al1, h1 & 1);
            u32* dst = &B_s[sk][sn0];
#pragma unroll
            for (int t = 0; t < 8; t++) {
                uint4 o;
                o.x = prmt(w0[2 * t],     w1[2 * t],     0x5410);
                o.y = prmt(w0[2 * t],     w1[2 * t],     0x7632);
                o.z = prmt(w0[2 * t + 1], w1[2 * t + 1], 0x5410);
                o.w = prmt(w0[2 * t + 1], w1[2 * t + 1], 0x7632);
                *(uint4*)(dst + 4 * t) = o;
            }
        }
        __syncthreads();
#pragma unroll
        for (int s = 0; s < 4; s++) {
            const int k2b = s * 8;
            u32 a[2][4], bf[4][2];
#pragma unroll
            for (int mi = 0; mi < 2; mi++) {
                a[mi][0] = A_s[k2b + tig][mi * 16 + gid];
                a[mi][1] = A_s[k2b + tig][mi * 16 + gid + 8];
                a[mi][2] = A_s[k2b + tig + 4][mi * 16 + gid];
                a[mi][3] = A_s[k2b + tig + 4][mi * 16 + gid + 8];
            }
#pragma unroll
            for (int ni = 0; ni < 4; ni++) {
                bf[ni][0] = B_s[k2b + tig][n0w + ni * 8 + gid];
                bf[ni][1] = B_s[k2b + tig + 4][n0w + ni * 8 + gid];
            }
#pragma unroll
            for (int mi = 0; mi < 2; mi++)
#pragma unroll
                for (int ni = 0; ni < 4; ni++)
                    MMA_F16(acc[mi][ni], a[mi][0], a[mi][1], a[mi][2], a[mi][3],
                            bf[ni][0], bf[ni][1]);
        }
        __syncthreads();
    }

#pragma unroll
    for (int mi = 0; mi < 2; mi++)
#pragma unroll
        for (int h = 0; h < 2; h++) {
            const int co = mi * 16 + gid + h * 8;
#pragma unroll
            for (int ni = 0; ni < 4; ni++) {
                const int ng = p0 + n0w + ni * 8 + 2 * tig;
                const int oh = ng >> hw_shift, ow = ng & (HW - 1);
                float2 o = {acc[mi][ni][h * 2], acc[mi][ni][h * 2 + 1]};
                *(float2*)&out[((size_t)(b * 32 + co) * HW + oh) * HW + ow] = o;
            }
        }
}

// ===========================================================================
extern "C" void kernel_launch(void* const* d_in, const int* in_sizes, int n_in,
                              void* d_out, int out_size)
{
    (void)in_sizes; (void)n_in;
    const float* x       = (const float*)d_in[0];
    const float* enc_w1  = (const float*)d_in[1];
    const float* enc_b1  = (const float*)d_in[2];
    const float* enc_w2  = (const float*)d_in[3];
    const float* enc_b2  = (const float*)d_in[4];
    const float* enc_w3  = (const float*)d_in[5];
    const float* enc_b3  = (const float*)d_in[6];
    const float* enc_rw3 = (const float*)d_in[7];
    const float* enc_rw1 = (const float*)d_in[8];
    const float* prevq_w = (const float*)d_in[9];
    const float* prevq_b = (const float*)d_in[10];
    const float* emb     = (const float*)d_in[11];
    const float* dec_w1  = (const float*)d_in[12];
    const float* dec_b1  = (const float*)d_in[13];
    const float* dec_rw3 = (const float*)d_in[14];
    const float* dec_rw1 = (const float*)d_in[15];
    const float* dec_w2  = (const float*)d_in[16];
    const float* dec_b2  = (const float*)d_in[17];
    const float* dec_w3  = (const float*)d_in[18];
    const float* dec_b3  = (const float*)d_in[19];
    float* out = (float*)d_out;

    float *b0, *b1, *b2, *b3, *ze, *loss;
    u32 *wt, *mx, *m0, *m1, *me, *mq;
    cudaGetSymbolAddress((void**)&b0, g_b0);
    cudaGetSymbolAddress((void**)&b1, g_b1);
    cudaGetSymbolAddress((void**)&b2, g_b2);
    cudaGetSymbolAddress((void**)&b3, g_b3);
    cudaGetSymbolAddress((void**)&ze, g_ze);
    cudaGetSymbolAddress((void**)&loss, g_loss);
    cudaGetSymbolAddress((void**)&wt, g_wt);
    cudaGetSymbolAddress((void**)&mx, g_mx);
    cudaGetSymbolAddress((void**)&m0, g_m0);
    cudaGetSymbolAddress((void**)&m1, g_m1);
    cudaGetSymbolAddress((void**)&me, g_me);
    cudaGetSymbolAddress((void**)&mq, g_mq);

    const int DSM = 4 * CHBUF * 4;   // 69632 bytes
    cudaFuncSetAttribute(conv4s2_tcf, cudaFuncAttributeMaxDynamicSharedMemorySize, DSM);
    cudaFuncSetAttribute(tconv_tcf,   cudaFuncAttributeMaxDynamicSharedMemorySize, DSM);

    // ---- encoder ----
    cvt_mirror<<<dim3(134, 128), 256>>>(x, mx, 256, 256, 258, 132, 0, 3, 2);
    wt4s2_f16<<<16, 256>>>(enc_w1, wt, 4, 128, 3);
    conv4s2_tcf<<<dim3(1, 128, 32), 128, DSM>>>(mx, wt, enc_b1, nullptr,
        4, 128, 258, 132, 128, 128, 7, 1, 0, (u16*)m0, 130, 136);

    wt4s2_f16<<<1024, 256>>>(enc_w2, wt, 128, 256, 128);
    conv4s2_tcf<<<dim3(1, 32, 64), 128, DSM>>>(m0, wt, enc_b2, nullptr,
        128, 256, 130, 68, 64, 64, 6, 1, 0, (u16*)m1, 66, 72);

    wt4s2_f16<<<4096, 256>>>(enc_w3, wt, 256, 512, 256);
    conv4s2_tcf<<<dim3(1, 8, 128), 128, DSM>>>(m1, wt, enc_b3, b2,
        256, 512, 66, 36, 32, 32, 5, 0, 1, (u16*)me, 34, 40);

    wt3_f16<<<288, 256>>>(enc_rw3, wt, 512);
    for (int l = 0; l < 2; l++) {
        conv3x3_tcf<<<dim3(4, 1, 32), 256>>>(me, wt, b3, 512, 32, 5, 34, 20);
        conv1x1_kernel<<<dim3(16, 8, 32), 256>>>(b3, enc_rw1, nullptr, b2,
            32, 512, 1024, 1, 1, 1, l == 0 ? (u16*)me : nullptr, 34, 40, 5, 31);
    }
    conv1x1_kernel<<<dim3(16, 1, 32), 256>>>(b2, prevq_w, prevq_b, ze,
        512, 64, 1024, 1, 0, 1, nullptr, 0, 0, 5, 31);

    // ---- VQ ----
    zero_loss_kernel<<<1, 1>>>(loss);
    vq_kernel<<<256, 128>>>(ze, emb, (u16*)mq, loss);
    finish_loss_kernel<<<1, 1>>>(loss, out + (out_size - 1));

    // ---- decoder ----
    wtT_f16<<<512, 256>>>(dec_w1, wt, 64, 256);
    tconv_tcf<<<dim3(1, 8, 256), 128, DSM>>>(mq, wt, dec_b1, b1,
        64, 256, 32, 32, 34, 20, 5, 0, 1, (u16*)m1, 66, 72);

    wt3_f16<<<144, 256>>>(dec_rw3, wt, 256);
    for (int l = 0; l < 2; l++) {
        conv3x3_tcf<<<dim3(16, 1, 32), 256>>>(m1, wt, b3, 256, 64, 6, 66, 36);
        conv1x1_kernel<<<dim3(64, 4, 32), 256>>>(b3, dec_rw1, nullptr, b1,
            32, 256, 4096, 1, 1, l == 0 ? 1 : 0, (u16*)m1, 66, 72, 6, 63);
    }

    wtT_f16<<<1024, 256>>>(dec_w2, wt, 256, 128);
    tconv_tcf<<<dim3(1, 32, 128), 128, DSM>>>(m1, wt, dec_b2, b0,
        256, 128, 64, 64, 66, 36, 6, 1, 1, nullptr, 0, 0);

    tconv_kernel<4, 1, 16, 16><<<dim3(8, 8, 32), 256>>>(b0, dec_w3, dec_b3, out, 128, 3, 128, 128, 0, 0);
}